// round 4
// baseline (speedup 1.0000x reference)
#include <cuda_runtime.h>
#include <math.h>
#include <stdint.h>

// Problem constants
#define NTOK 4096
#define DDIM 1024
#define HDIM 4096
#define NEXP 8
#define CAP  4096
#define NSLOT (NTOK*2)

// GEMM tiling: block 128x256, warp tile 64x64 (2x4 warps), BK=32, 3-stage cp.async
#define TM 128
#define TN 256
#define BK 32
#define BKP 36              // padded row in floats (36 mod 32 = 4 -> conflict-free)
#define NPIPE 3
#define ASTAGE_F (TM*BKP)   // floats
#define BSTAGE_F (TN*BKP)
#define STAGE_F  (ASTAGE_F+BSTAGE_F)   // 13824 floats = 55296 B
#define SMEM_BYTES (NPIPE*STAGE_F*4)   // 165888

// ---------------- scratch ----------------------------------------------------
__device__ int   g_cnt[NEXP];
__device__ int   g_off[NEXP];
__device__ int   g_etok[NEXP * CAP];
__device__ float g_egate[NEXP * CAP];
__device__ float g_h[(size_t)NSLOT * HDIM];            // 134 MB hidden acts
__device__ float g_ypart[(size_t)2 * NSLOT * DDIM];    // 67 MB (split-K=2 slabs)

// ---------------- helpers ----------------------------------------------------
__device__ __forceinline__ uint32_t smem_u32(const void* p) {
    uint32_t a;
    asm("{ .reg .u64 t; cvta.to.shared.u64 t, %1; cvt.u32.u64 %0, t; }"
        : "=r"(a) : "l"(p));
    return a;
}
__device__ __forceinline__ unsigned f2tf(float f) {
    unsigned r;
    asm("cvt.rna.tf32.f32 %0, %1;" : "=r"(r) : "f"(f));
    return r;
}
__device__ __forceinline__ void mma_tf32(float c[4], const unsigned a[4],
                                         const unsigned b[2]) {
    asm volatile(
        "mma.sync.aligned.m16n8k8.row.col.f32.tf32.tf32.f32 "
        "{%0,%1,%2,%3}, {%4,%5,%6,%7}, {%8,%9}, {%0,%1,%2,%3};"
        : "+f"(c[0]), "+f"(c[1]), "+f"(c[2]), "+f"(c[3])
        : "r"(a[0]), "r"(a[1]), "r"(a[2]), "r"(a[3]), "r"(b[0]), "r"(b[1]));
}
#define CPASYNC16(dst, src) \
    asm volatile("cp.async.cg.shared.global [%0], [%1], 16;" \
                 :: "r"(dst), "l"(src) : "memory")
#define CP_COMMIT() asm volatile("cp.async.commit_group;" ::: "memory")
#define CP_WAIT(n)  asm volatile("cp.async.wait_group %0;" :: "n"(n) : "memory")

// ---------------- small kernels ----------------------------------------------
__global__ void init_kernel() {
    if (threadIdx.x < NEXP) g_cnt[threadIdx.x] = 0;
}
__global__ void prefix_kernel() {
    if (threadIdx.x == 0) {
        int s = 0;
        for (int e = 0; e < NEXP; e++) { g_off[e] = s; s += g_cnt[e]; }
    }
}

// ---------------- router (fp32-exact) ----------------------------------------
__global__ __launch_bounds__(256) void router_kernel(
    const float* __restrict__ x, const float* __restrict__ Wr,
    const float* __restrict__ br) {
    __shared__ float sWr[NEXP * DDIM];
    int tid = threadIdx.x;
    for (int i = tid; i < NEXP * DDIM; i += 256) sWr[i] = Wr[i];
    __syncthreads();
    int warp = tid >> 5, lane = tid & 31;
    int tok = blockIdx.x * 8 + warp;
    if (tok >= NTOK) return;
    const float* xr = x + (size_t)tok * DDIM;
    float acc[NEXP];
#pragma unroll
    for (int e = 0; e < NEXP; e++) acc[e] = 0.f;
    for (int d = lane; d < DDIM; d += 32) {
        float xv = xr[d];
#pragma unroll
        for (int e = 0; e < NEXP; e++) acc[e] += xv * sWr[e * DDIM + d];
    }
#pragma unroll
    for (int e = 0; e < NEXP; e++)
#pragma unroll
        for (int o = 16; o > 0; o >>= 1)
            acc[e] += __shfl_down_sync(0xffffffffu, acc[e], o);
    if (lane == 0) {
        float v0 = -3.4e38f, v1 = -3.4e38f;
        int i0 = 0, i1 = 0;
#pragma unroll
        for (int e = 0; e < NEXP; e++) {
            float l = acc[e] + br[e];
            if (l > v0) { v1 = v0; i1 = i0; v0 = l; i0 = e; }
            else if (l > v1) { v1 = l; i1 = e; }
        }
        float t = expf(v1 - v0);
        float inv = 1.f / (1.f + t);
        int p0 = atomicAdd(&g_cnt[i0], 1);
        g_etok[i0 * CAP + p0] = tok * 2;
        g_egate[i0 * CAP + p0] = inv;
        int p1 = atomicAdd(&g_cnt[i1], 1);
        g_etok[i1 * CAP + p1] = tok * 2 + 1;
        g_egate[i1 * CAP + p1] = t * inv;
    }
}

// ---------------- grouped GEMM (tf32 mma.sync, cp.async pipeline) ------------
// MODE 1: g_h = relu(gather(x) @ W1[e]^T + b1[e])   KITER=32 (K=1024), kz=0
// MODE 2: ypart[kz] = gate*(h @ W2[e]^T [+ b2])     KITER=64 (K-half=2048), kz=0,1
template <int KITER, int MODE>
__global__ __launch_bounds__(256) void moe_mma_kernel(
    const float* __restrict__ Aglob, const float* __restrict__ Bglob,
    const float* __restrict__ bias) {
    const int NTOT = (MODE == 1) ? HDIM : DDIM;
    const int KFULL = (MODE == 1) ? DDIM : HDIM;
    int z = blockIdx.z;
    int e = z & 7, kz = z >> 3;
    int cnt = g_cnt[e];
    int m0 = blockIdx.y * TM;
    if (m0 >= cnt) return;
    int n0 = blockIdx.x * TN;
    int off = g_off[e];
    int k0g = kz * (KITER * BK);

    extern __shared__ float sm[];
    __shared__ int sRow[TM];
    __shared__ float sGate[TM];

    int tid = threadIdx.x;
    for (int r = tid; r < TM; r += 256) {
        int slot = m0 + r;
        if (MODE == 1) {
            sRow[r] = (slot < cnt) ? (g_etok[e * CAP + slot] >> 1) : 0;
        } else {
            sRow[r] = (slot < cnt) ? g_etok[e * CAP + slot] : 0;
            sGate[r] = (slot < cnt) ? g_egate[e * CAP + slot] : 0.f;
        }
    }
    __syncthreads();

    // ---- producer setup (all 256 threads produce and consume) ----
    int ar = tid & 127;
    int aseg0 = (tid >> 7) * 4;           // 4 of the 8 16B-segments per A row
    const float* aRow;
    if (MODE == 1) {
        aRow = Aglob + (size_t)sRow[ar] * KFULL + k0g;
    } else {
        int sg = off + m0 + ar;
        if (sg > NSLOT - 1) sg = NSLOT - 1;
        aRow = g_h + (size_t)sg * KFULL + k0g;
    }
    const float* bRow = Bglob + (size_t)e * NTOT * KFULL +
                        (size_t)(n0 + tid) * KFULL + k0g;
    uint32_t sbase = smem_u32(sm);
    uint32_t aDst = sbase + (ar * BKP + aseg0 * 4) * 4;
    uint32_t bDst = sbase + (ASTAGE_F + tid * BKP) * 4;

#define ISSUE(c)                                                         \
    {                                                                    \
        int st_ = (c) % NPIPE;                                           \
        uint32_t ad_ = aDst + st_ * (STAGE_F * 4);                       \
        const float* ag_ = aRow + (c) * BK + aseg0 * 4;                  \
        _Pragma("unroll")                                                \
        for (int s2 = 0; s2 < 4; s2++)                                   \
            CPASYNC16(ad_ + s2 * 16, ag_ + s2 * 4);                      \
        uint32_t bd_ = bDst + st_ * (STAGE_F * 4);                       \
        const float* bg_ = bRow + (c) * BK;                              \
        _Pragma("unroll")                                                \
        for (int s2 = 0; s2 < 8; s2++)                                   \
            CPASYNC16(bd_ + s2 * 16, bg_ + s2 * 4);                      \
    }

    // prologue: stages 0..NPIPE-2
#pragma unroll
    for (int c = 0; c < NPIPE - 1; c++) {
        ISSUE(c);
        CP_COMMIT();
    }

    // ---- consumer setup ----
    int wid = tid >> 5, lane = tid & 31;
    int wm = wid >> 2, wn = wid & 3;      // 2 x 4 warps
    int g = lane >> 2, tig = lane & 3;

    float acc[4][8][4];
#pragma unroll
    for (int mf = 0; mf < 4; mf++)
#pragma unroll
        for (int nf = 0; nf < 8; nf++)
#pragma unroll
            for (int v = 0; v < 4; v++) acc[mf][nf][v] = 0.f;

    for (int c = 0; c < KITER; c++) {
        CP_WAIT(NPIPE - 2);     // chunk c resident
        __syncthreads();        // all data visible; prior stage compute done
        if (c + NPIPE - 1 < KITER) ISSUE(c + NPIPE - 1);
        CP_COMMIT();            // always commit (keeps group accounting fixed)

        int st = c % NPIPE;
        const float* As_ = sm + st * STAGE_F;
        const float* Bs_ = As_ + ASTAGE_F;
#pragma unroll
        for (int kk = 0; kk < BK; kk += 8) {
            unsigned a[4][4], b[8][2];
#pragma unroll
            for (int mf = 0; mf < 4; mf++) {
                int r = wm * 64 + mf * 16 + g;
                a[mf][0] = f2tf(As_[r * BKP + kk + tig]);
                a[mf][1] = f2tf(As_[(r + 8) * BKP + kk + tig]);
                a[mf][2] = f2tf(As_[r * BKP + kk + tig + 4]);
                a[mf][3] = f2tf(As_[(r + 8) * BKP + kk + tig + 4]);
            }
#pragma unroll
            for (int nf = 0; nf < 8; nf++) {
                int cc = wn * 64 + nf * 8 + g;
                b[nf][0] = f2tf(Bs_[cc * BKP + kk + tig]);
                b[nf][1] = f2tf(Bs_[cc * BKP + kk + tig + 4]);
            }
#pragma unroll
            for (int mf = 0; mf < 4; mf++)
#pragma unroll
                for (int nf = 0; nf < 8; nf++)
                    mma_tf32(acc[mf][nf], a[mf], b[nf]);
        }
    }
#undef ISSUE

    // ---- epilogue ----
#pragma unroll
    for (int mf = 0; mf < 4; mf++) {
#pragma unroll
        for (int hh = 0; hh < 2; hh++) {
            int r = wm * 64 + mf * 16 + g + 8 * hh;
            int slot = m0 + r;
            if (slot >= cnt) continue;
            if (MODE == 1) {
                float* orow = g_h + (size_t)(off + slot) * HDIM + n0;
                const float* bp = bias + e * HDIM + n0;
#pragma unroll
                for (int nf = 0; nf < 8; nf++) {
                    int col = wn * 64 + nf * 8 + 2 * tig;
                    float v0 = acc[mf][nf][hh * 2 + 0] + bp[col];
                    float v1 = acc[mf][nf][hh * 2 + 1] + bp[col + 1];
                    *(float2*)(orow + col) =
                        make_float2(fmaxf(v0, 0.f), fmaxf(v1, 0.f));
                }
            } else {
                int packed = sRow[r];
                float gte = sGate[r];
                float* orow = g_ypart +
                              ((size_t)kz * NSLOT + packed) * DDIM + n0;
                const float* bp = bias + e * DDIM + n0;
#pragma unroll
                for (int nf = 0; nf < 8; nf++) {
                    int col = wn * 64 + nf * 8 + 2 * tig;
                    float v0 = acc[mf][nf][hh * 2 + 0];
                    float v1 = acc[mf][nf][hh * 2 + 1];
                    if (kz == 0) { v0 += bp[col]; v1 += bp[col + 1]; }
                    *(float2*)(orow + col) = make_float2(v0 * gte, v1 * gte);
                }
            }
        }
    }
}

// ---------------- combine: sum 2 k-choices x 2 K-splits ----------------------
__global__ void combine_kernel(float* __restrict__ out) {
    int i = blockIdx.x * blockDim.x + threadIdx.x;
    const int TOT = NTOK * DDIM / 4;
    if (i >= TOT) return;
    int n = i / (DDIM / 4);
    int dg = i % (DDIM / 4);
    const float4* yp = (const float4*)g_ypart;
    const size_t RP = DDIM / 4;
    float4 a0 = yp[(size_t)(2 * n) * RP + dg];
    float4 a1 = yp[(size_t)(2 * n + 1) * RP + dg];
    float4 b0 = yp[((size_t)NSLOT + 2 * n) * RP + dg];
    float4 b1 = yp[((size_t)NSLOT + 2 * n + 1) * RP + dg];
    float4 r;
    r.x = (a0.x + a1.x) + (b0.x + b1.x);
    r.y = (a0.y + a1.y) + (b0.y + b1.y);
    r.z = (a0.z + a1.z) + (b0.z + b1.z);
    r.w = (a0.w + a1.w) + (b0.w + b1.w);
    ((float4*)out)[i] = r;
}

// ---------------- launch -----------------------------------------------------
extern "C" void kernel_launch(void* const* d_in, const int* in_sizes, int n_in,
                              void* d_out, int out_size) {
    const float* x  = (const float*)d_in[0];
    const float* Wr = (const float*)d_in[1];
    const float* br = (const float*)d_in[2];
    const float* W1 = (const float*)d_in[3];
    const float* b1 = (const float*)d_in[4];
    const float* W2 = (const float*)d_in[5];
    const float* b2 = (const float*)d_in[6];
    float* out = (float*)d_out;
    (void)in_sizes; (void)n_in; (void)out_size;

    cudaFuncSetAttribute(moe_mma_kernel<32, 1>,
                         cudaFuncAttributeMaxDynamicSharedMemorySize, SMEM_BYTES);
    cudaFuncSetAttribute(moe_mma_kernel<64, 2>,
                         cudaFuncAttributeMaxDynamicSharedMemorySize, SMEM_BYTES);

    init_kernel<<<1, 32>>>();
    router_kernel<<<NTOK / 8, 256>>>(x, Wr, br);
    prefix_kernel<<<1, 1>>>();

    dim3 g1(HDIM / TN, NTOK / TM, NEXP);       // 16 x 32 x 8
    moe_mma_kernel<32, 1><<<g1, 256, SMEM_BYTES>>>(x, W1, b1);

    dim3 g2(DDIM / TN, NTOK / TM, NEXP * 2);   // 4 x 32 x 16 (split-K=2)
    moe_mma_kernel<64, 2><<<g2, 256, SMEM_BYTES>>>(nullptr, W2, b2);

    combine_kernel<<<(NTOK * DDIM / 4 + 255) / 256, 256>>>(out);
}

// round 5
// speedup vs baseline: 2.6531x; 2.6531x over previous
#include <cuda_runtime.h>
#include <cuda_fp16.h>
#include <math.h>
#include <stdint.h>

// Problem constants
#define NTOK 4096
#define DDIM 1024
#define HDIM 4096
#define NEXP 8
#define CAP  4096
#define NSLOT (NTOK*2)

// fp16 GEMM tiling: block 128x128, warp 64x32 (2x4 warps), K-chunk 64 (128B rows)
#define TM 128
#define TN 128
#define BKH 64
#define NPIPE 3
#define ASTAGE_B (TM*128)            // 16384 B
#define BSTAGE_B (TN*128)            // 16384 B
#define STAGE_B  (ASTAGE_B+BSTAGE_B) // 32768 B
#define SMEM_BYTES (NPIPE*STAGE_B)   // 98304 B -> 2 CTAs/SM

// ---------------- scratch ----------------------------------------------------
__device__ int    g_cnt[NEXP];
__device__ int    g_off[NEXP];
__device__ int    g_etok[NEXP * CAP];
__device__ float  g_egate[NEXP * CAP];
__device__ __half g_xh[(size_t)NTOK * DDIM];          // 8 MB
__device__ __half g_w1h[(size_t)NEXP * HDIM * DDIM];  // 67 MB
__device__ __half g_w2h[(size_t)NEXP * DDIM * HDIM];  // 67 MB
__device__ __half g_h[(size_t)NSLOT * HDIM];          // 67 MB
__device__ float  g_ypart[(size_t)NSLOT * DDIM];      // 33.5 MB

// ---------------- helpers ----------------------------------------------------
__device__ __forceinline__ uint32_t smem_u32(const void* p) {
    uint32_t a;
    asm("{ .reg .u64 t; cvta.to.shared.u64 t, %1; cvt.u32.u64 %0, t; }"
        : "=r"(a) : "l"(p));
    return a;
}
__device__ __forceinline__ void mma16816(float c[4], const unsigned a[4],
                                         const unsigned b[2]) {
    asm volatile(
        "mma.sync.aligned.m16n8k16.row.col.f32.f16.f16.f32 "
        "{%0,%1,%2,%3}, {%4,%5,%6,%7}, {%8,%9}, {%0,%1,%2,%3};"
        : "+f"(c[0]), "+f"(c[1]), "+f"(c[2]), "+f"(c[3])
        : "r"(a[0]), "r"(a[1]), "r"(a[2]), "r"(a[3]), "r"(b[0]), "r"(b[1]));
}
#define LDSM_X4(r0, r1, r2, r3, addr)                                        \
    asm volatile("ldmatrix.sync.aligned.m8n8.x4.shared.b16 {%0,%1,%2,%3}, [%4];" \
                 : "=r"(r0), "=r"(r1), "=r"(r2), "=r"(r3) : "r"(addr))
#define CPASYNC16(dst, src) \
    asm volatile("cp.async.cg.shared.global [%0], [%1], 16;" \
                 :: "r"(dst), "l"(src) : "memory")
#define CP_COMMIT() asm volatile("cp.async.commit_group;" ::: "memory")
#define CP_WAIT(n)  asm volatile("cp.async.wait_group %0;" :: "n"(n) : "memory")

// ---------------- small kernels ----------------------------------------------
__global__ void init_kernel() {
    if (threadIdx.x < NEXP) g_cnt[threadIdx.x] = 0;
}
__global__ void prefix_kernel() {
    if (threadIdx.x == 0) {
        int s = 0;
        for (int e = 0; e < NEXP; e++) { g_off[e] = s; s += g_cnt[e]; }
    }
}
// fp32 -> fp16 streaming convert (8 elems/thread)
__global__ __launch_bounds__(256) void cvt_kernel(const float* __restrict__ in,
                                                  __half* __restrict__ out,
                                                  int n8) {
    int i = blockIdx.x * 256 + threadIdx.x;
    if (i >= n8) return;
    size_t base = (size_t)i * 8;
    float4 v0 = *(const float4*)(in + base);
    float4 v1 = *(const float4*)(in + base + 4);
    __half2 h0 = __floats2half2_rn(v0.x, v0.y);
    __half2 h1 = __floats2half2_rn(v0.z, v0.w);
    __half2 h2 = __floats2half2_rn(v1.x, v1.y);
    __half2 h3 = __floats2half2_rn(v1.z, v1.w);
    uint4 u;
    u.x = *(uint32_t*)&h0; u.y = *(uint32_t*)&h1;
    u.z = *(uint32_t*)&h2; u.w = *(uint32_t*)&h3;
    *(uint4*)(out + base) = u;
}

// ---------------- router (fp32-exact) ----------------------------------------
__global__ __launch_bounds__(256) void router_kernel(
    const float* __restrict__ x, const float* __restrict__ Wr,
    const float* __restrict__ br) {
    __shared__ float sWr[NEXP * DDIM];
    int tid = threadIdx.x;
    for (int i = tid; i < NEXP * DDIM; i += 256) sWr[i] = Wr[i];
    __syncthreads();
    int warp = tid >> 5, lane = tid & 31;
    int tok = blockIdx.x * 8 + warp;
    if (tok >= NTOK) return;
    const float* xr = x + (size_t)tok * DDIM;
    float acc[NEXP];
#pragma unroll
    for (int e = 0; e < NEXP; e++) acc[e] = 0.f;
    for (int d = lane; d < DDIM; d += 32) {
        float xv = xr[d];
#pragma unroll
        for (int e = 0; e < NEXP; e++) acc[e] += xv * sWr[e * DDIM + d];
    }
#pragma unroll
    for (int e = 0; e < NEXP; e++)
#pragma unroll
        for (int o = 16; o > 0; o >>= 1)
            acc[e] += __shfl_down_sync(0xffffffffu, acc[e], o);
    if (lane == 0) {
        float v0 = -3.4e38f, v1 = -3.4e38f;
        int i0 = 0, i1 = 0;
#pragma unroll
        for (int e = 0; e < NEXP; e++) {
            float l = acc[e] + br[e];
            if (l > v0) { v1 = v0; i1 = i0; v0 = l; i0 = e; }
            else if (l > v1) { v1 = l; i1 = e; }
        }
        float t = expf(v1 - v0);
        float inv = 1.f / (1.f + t);
        int p0 = atomicAdd(&g_cnt[i0], 1);
        g_etok[i0 * CAP + p0] = tok * 2;
        g_egate[i0 * CAP + p0] = inv;
        int p1 = atomicAdd(&g_cnt[i1], 1);
        g_etok[i1 * CAP + p1] = tok * 2 + 1;
        g_egate[i1 * CAP + p1] = t * inv;
    }
}

// ---------------- fp16 grouped GEMM (ldmatrix + cp.async pipeline) ------------
// MODE 1: g_h(fp16) = relu(gather(g_xh) @ g_w1h[e]^T + b1[e])   KITER=16
// MODE 2: g_ypart(f32) = gate*(g_h @ g_w2h[e]^T + b2[e])        KITER=64
template <int KITER, int MODE>
__global__ __launch_bounds__(256, 2) void moe_hgemm(
    const __half* __restrict__ Ah, const __half* __restrict__ Bh,
    const float* __restrict__ bias) {
    const int NTOT = (MODE == 1) ? HDIM : DDIM;
    const int KFULL = (MODE == 1) ? DDIM : HDIM;
    int e = blockIdx.z;
    int cnt = g_cnt[e];
    int m0 = blockIdx.y * TM;
    if (m0 >= cnt) return;
    int n0 = blockIdx.x * TN;
    int off = g_off[e];

    extern __shared__ __align__(1024) char sm[];
    __shared__ int sRow[TM];
    __shared__ float sGate[TM];

    int tid = threadIdx.x;
    for (int r = tid; r < TM; r += 256) {
        int slot = m0 + r;
        if (MODE == 1) {
            sRow[r] = (slot < cnt) ? (g_etok[e * CAP + slot] >> 1) : 0;
        } else {
            sRow[r] = (slot < cnt) ? g_etok[e * CAP + slot] : 0;
            sGate[r] = (slot < cnt) ? g_egate[e * CAP + slot] : 0.f;
        }
    }
    __syncthreads();

    // ---- producer mapping: thread -> (row = tid/2, 4 of 8 16B chunks) ----
    int prow = tid >> 1;
    int c0 = (tid & 1) * 4;
    int psw = prow & 7;
    const __half* aRow;
    if (MODE == 1) {
        aRow = Ah + (size_t)sRow[prow] * KFULL;
    } else {
        int sg = off + m0 + prow;
        if (sg > NSLOT - 1) sg = NSLOT - 1;
        aRow = g_h + (size_t)sg * KFULL;
    }
    const __half* bRow = Bh + (size_t)e * NTOT * KFULL +
                         (size_t)(n0 + prow) * KFULL;
    uint32_t sb = smem_u32(sm);
    uint32_t aDstBase = sb + prow * 128;
    uint32_t bDstBase = sb + ASTAGE_B + prow * 128;

#define ISSUE(c)                                                      \
    {                                                                 \
        uint32_t so_ = ((c) % NPIPE) * STAGE_B;                       \
        const __half* ag_ = aRow + (c)*BKH;                           \
        const __half* bg_ = bRow + (c)*BKH;                           \
        _Pragma("unroll")                                             \
        for (int j = 0; j < 4; j++) {                                 \
            int cc = c0 + j;                                          \
            int sc = cc ^ psw;                                        \
            CPASYNC16(aDstBase + so_ + sc * 16, ag_ + cc * 8);        \
            CPASYNC16(bDstBase + so_ + sc * 16, bg_ + cc * 8);        \
        }                                                             \
    }

#pragma unroll
    for (int c = 0; c < NPIPE - 1; c++) {
        ISSUE(c);
        CP_COMMIT();
    }

    // ---- consumer mapping ----
    int lane = tid & 31, wid = tid >> 5;
    int wm = wid >> 2, wn = wid & 3;          // 2 x 4 warps, warp tile 64x32
    int s = lane & 7;
    int aChunkBit = lane >> 4;                 // matrices 0,1 lo / 2,3 hi
    uint32_t aByte = (uint32_t)(wm * 64 + (lane & 7) + ((lane >> 3) & 1) * 8) * 128;
    int bChunkBit = (lane >> 3) & 1;
    uint32_t bByte = ASTAGE_B +
                     (uint32_t)(wn * 32 + ((lane >> 4) & 1) * 8 + (lane & 7)) * 128;

    float acc[4][4][4];
#pragma unroll
    for (int mt = 0; mt < 4; mt++)
#pragma unroll
        for (int nt = 0; nt < 4; nt++)
#pragma unroll
            for (int v = 0; v < 4; v++) acc[mt][nt][v] = 0.f;

    for (int c = 0; c < KITER; c++) {
        CP_WAIT(NPIPE - 2);
        __syncthreads();
        if (c + NPIPE - 1 < KITER) ISSUE(c + NPIPE - 1);
        CP_COMMIT();

        uint32_t stb = sb + (c % NPIPE) * STAGE_B;
#pragma unroll
        for (int kt = 0; kt < 4; kt++) {
            unsigned af[4][4], bf[4][2];
#pragma unroll
            for (int mt = 0; mt < 4; mt++) {
                uint32_t ad = stb + aByte + mt * 2048 +
                              (uint32_t)(((2 * kt + aChunkBit) ^ s) << 4);
                LDSM_X4(af[mt][0], af[mt][1], af[mt][2], af[mt][3], ad);
            }
#pragma unroll
            for (int p = 0; p < 2; p++) {
                uint32_t bd = stb + bByte + p * 2048 +
                              (uint32_t)(((2 * kt + bChunkBit) ^ s) << 4);
                LDSM_X4(bf[2 * p][0], bf[2 * p][1], bf[2 * p + 1][0],
                        bf[2 * p + 1][1], bd);
            }
#pragma unroll
            for (int mt = 0; mt < 4; mt++)
#pragma unroll
                for (int nt = 0; nt < 4; nt++)
                    mma16816(acc[mt][nt], af[mt], bf[nt]);
        }
    }
#undef ISSUE

    // ---- epilogue ----
    int g = lane >> 2, tig = lane & 3;
#pragma unroll
    for (int mt = 0; mt < 4; mt++) {
#pragma unroll
        for (int hh = 0; hh < 2; hh++) {
            int r = wm * 64 + mt * 16 + g + 8 * hh;
            int slot = m0 + r;
            if (slot >= cnt) continue;
            if (MODE == 1) {
                __half* orow = g_h + (size_t)(off + slot) * HDIM + n0;
                const float* bp = bias + e * HDIM + n0;
#pragma unroll
                for (int nt = 0; nt < 4; nt++) {
                    int col = wn * 32 + nt * 8 + 2 * tig;
                    float v0 = fmaxf(acc[mt][nt][hh * 2 + 0] + bp[col], 0.f);
                    float v1 = fmaxf(acc[mt][nt][hh * 2 + 1] + bp[col + 1], 0.f);
                    __half2 hv = __floats2half2_rn(v0, v1);
                    *(__half2*)(orow + col) = hv;
                }
            } else {
                int packed = sRow[r];
                float gte = sGate[r];
                float* orow = g_ypart + (size_t)packed * DDIM + n0;
                const float* bp = bias + e * DDIM + n0;
#pragma unroll
                for (int nt = 0; nt < 4; nt++) {
                    int col = wn * 32 + nt * 8 + 2 * tig;
                    float v0 = (acc[mt][nt][hh * 2 + 0] + bp[col]) * gte;
                    float v1 = (acc[mt][nt][hh * 2 + 1] + bp[col + 1]) * gte;
                    *(float2*)(orow + col) = make_float2(v0, v1);
                }
            }
        }
    }
}

// ---------------- combine -----------------------------------------------------
__global__ void combine_kernel(float* __restrict__ out) {
    int i = blockIdx.x * blockDim.x + threadIdx.x;
    const int TOT = NTOK * DDIM / 4;
    if (i >= TOT) return;
    int n = i / (DDIM / 4);
    int dg = i % (DDIM / 4);
    const float4* yp = (const float4*)g_ypart;
    const size_t RP = DDIM / 4;
    float4 a = yp[(size_t)(2 * n) * RP + dg];
    float4 b = yp[(size_t)(2 * n + 1) * RP + dg];
    float4 r;
    r.x = a.x + b.x; r.y = a.y + b.y; r.z = a.z + b.z; r.w = a.w + b.w;
    ((float4*)out)[i] = r;
}

// ---------------- launch -----------------------------------------------------
extern "C" void kernel_launch(void* const* d_in, const int* in_sizes, int n_in,
                              void* d_out, int out_size) {
    const float* x  = (const float*)d_in[0];
    const float* Wr = (const float*)d_in[1];
    const float* br = (const float*)d_in[2];
    const float* W1 = (const float*)d_in[3];
    const float* b1 = (const float*)d_in[4];
    const float* W2 = (const float*)d_in[5];
    const float* b2 = (const float*)d_in[6];
    float* out = (float*)d_out;
    (void)in_sizes; (void)n_in; (void)out_size;

    cudaFuncSetAttribute(moe_hgemm<16, 1>,
                         cudaFuncAttributeMaxDynamicSharedMemorySize, SMEM_BYTES);
    cudaFuncSetAttribute(moe_hgemm<64, 2>,
                         cudaFuncAttributeMaxDynamicSharedMemorySize, SMEM_BYTES);

    init_kernel<<<1, 32>>>();

    __half *xh, *w1h, *w2h;
    cudaGetSymbolAddress((void**)&xh, g_xh);
    cudaGetSymbolAddress((void**)&w1h, g_w1h);
    cudaGetSymbolAddress((void**)&w2h, g_w2h);
    {
        int n8 = NTOK * DDIM / 8;
        cvt_kernel<<<(n8 + 255) / 256, 256>>>(x, xh, n8);
    }
    {
        int n8 = NEXP * HDIM * DDIM / 8;
        cvt_kernel<<<(n8 + 255) / 256, 256>>>(W1, w1h, n8);
        cvt_kernel<<<(n8 + 255) / 256, 256>>>(W2, w2h, n8);
    }

    router_kernel<<<NTOK / 8, 256>>>(x, Wr, br);
    prefix_kernel<<<1, 1>>>();

    dim3 g1(HDIM / TN, NTOK / TM, NEXP);   // 32 x 32 x 8
    moe_hgemm<16, 1><<<g1, 256, SMEM_BYTES>>>(xh, w1h, b1);

    dim3 g2(DDIM / TN, NTOK / TM, NEXP);   // 8 x 32 x 8
    moe_hgemm<64, 2><<<g2, 256, SMEM_BYTES>>>(nullptr, w2h, b2);

    combine_kernel<<<(NTOK * DDIM / 4 + 255) / 256, 256>>>(out);
}

// round 6
// speedup vs baseline: 2.6855x; 1.0122x over previous
#include <cuda_runtime.h>
#include <cuda_fp16.h>
#include <math.h>
#include <stdint.h>

// Problem constants
#define NTOK 4096
#define DDIM 1024
#define HDIM 4096
#define NEXP 8
#define CAP  4096
#define NSLOT (NTOK*2)

// fp16 GEMM tiling: block 128x128, warp 64x32 (2x4 warps), K-chunk 64 (128B rows)
#define TM 128
#define TN 128
#define BKH 64
#define NPIPE 3
#define ASTAGE_B (TM*128)
#define BSTAGE_B (TN*128)
#define STAGE_B  (ASTAGE_B+BSTAGE_B)
#define SMEM_BYTES (NPIPE*STAGE_B)   // 98304 B -> 2 CTAs/SM

// ---------------- scratch ----------------------------------------------------
__device__ int    g_cnt[NEXP];
__device__ int    g_etok[NEXP * CAP];
__device__ float  g_egate[NEXP * CAP];
__device__ __half g_xh[(size_t)NTOK * DDIM];
__device__ __half g_w1h[(size_t)NEXP * HDIM * DDIM];
__device__ __half g_w2h[(size_t)NEXP * DDIM * HDIM];
__device__ __half g_h[(size_t)NSLOT * HDIM];
__device__ float  g_ypart[(size_t)2 * NSLOT * DDIM];   // 2 K-splits

// ---------------- helpers ----------------------------------------------------
__device__ __forceinline__ uint32_t smem_u32(const void* p) {
    uint32_t a;
    asm("{ .reg .u64 t; cvta.to.shared.u64 t, %1; cvt.u32.u64 %0, t; }"
        : "=r"(a) : "l"(p));
    return a;
}
__device__ __forceinline__ void mma16816(float c[4], const unsigned a[4],
                                         const unsigned b[2]) {
    asm volatile(
        "mma.sync.aligned.m16n8k16.row.col.f32.f16.f16.f32 "
        "{%0,%1,%2,%3}, {%4,%5,%6,%7}, {%8,%9}, {%0,%1,%2,%3};"
        : "+f"(c[0]), "+f"(c[1]), "+f"(c[2]), "+f"(c[3])
        : "r"(a[0]), "r"(a[1]), "r"(a[2]), "r"(a[3]), "r"(b[0]), "r"(b[1]));
}
#define LDSM_X4(r0, r1, r2, r3, addr)                                        \
    asm volatile("ldmatrix.sync.aligned.m8n8.x4.shared.b16 {%0,%1,%2,%3}, [%4];" \
                 : "=r"(r0), "=r"(r1), "=r"(r2), "=r"(r3) : "r"(addr))
#define CPASYNC16(dst, src) \
    asm volatile("cp.async.cg.shared.global [%0], [%1], 16;" \
                 :: "r"(dst), "l"(src) : "memory")
#define CP_COMMIT() asm volatile("cp.async.commit_group;" ::: "memory")
#define CP_WAIT(n)  asm volatile("cp.async.wait_group %0;" :: "n"(n) : "memory")

// ---------------- cvt (W1 variant also zeroes counters) -----------------------
template <int INIT>
__global__ __launch_bounds__(256) void cvt_kernel(const float* __restrict__ in,
                                                  __half* __restrict__ out,
                                                  int n8) {
    int i = blockIdx.x * 256 + threadIdx.x;
    if (INIT && i < NEXP) g_cnt[i] = 0;
    if (i >= n8) return;
    size_t base = (size_t)i * 8;
    float4 v0 = *(const float4*)(in + base);
    float4 v1 = *(const float4*)(in + base + 4);
    __half2 h0 = __floats2half2_rn(v0.x, v0.y);
    __half2 h1 = __floats2half2_rn(v0.z, v0.w);
    __half2 h2 = __floats2half2_rn(v1.x, v1.y);
    __half2 h3 = __floats2half2_rn(v1.z, v1.w);
    uint4 u;
    u.x = *(uint32_t*)&h0; u.y = *(uint32_t*)&h1;
    u.z = *(uint32_t*)&h2; u.w = *(uint32_t*)&h3;
    *(uint4*)(out + base) = u;
}

// ---------------- router (fp32-exact) + x->fp16 convert -----------------------
__global__ __launch_bounds__(256) void router_kernel(
    const float* __restrict__ x, const float* __restrict__ Wr,
    const float* __restrict__ br) {
    __shared__ float sWr[NEXP * DDIM];
    int tid = threadIdx.x;
    for (int i = tid; i < NEXP * DDIM; i += 256) sWr[i] = Wr[i];
    __syncthreads();
    int warp = tid >> 5, lane = tid & 31;
    int tok = blockIdx.x * 8 + warp;
    if (tok >= NTOK) return;
    const float* xr = x + (size_t)tok * DDIM;
    __half* xo = g_xh + (size_t)tok * DDIM;
    float acc[NEXP];
#pragma unroll
    for (int e = 0; e < NEXP; e++) acc[e] = 0.f;
#pragma unroll
    for (int i = 0; i < DDIM / 128; i++) {
        int d = i * 128 + lane * 4;
        float4 xv = *(const float4*)(xr + d);
        __half2 h0 = __floats2half2_rn(xv.x, xv.y);
        __half2 h1 = __floats2half2_rn(xv.z, xv.w);
        uint2 u;
        u.x = *(uint32_t*)&h0; u.y = *(uint32_t*)&h1;
        *(uint2*)(xo + d) = u;
#pragma unroll
        for (int e = 0; e < NEXP; e++) {
            const float* w = sWr + e * DDIM + d;
            acc[e] += xv.x * w[0] + xv.y * w[1] + xv.z * w[2] + xv.w * w[3];
        }
    }
#pragma unroll
    for (int e = 0; e < NEXP; e++)
#pragma unroll
        for (int o = 16; o > 0; o >>= 1)
            acc[e] += __shfl_down_sync(0xffffffffu, acc[e], o);
    if (lane == 0) {
        float v0 = -3.4e38f, v1 = -3.4e38f;
        int i0 = 0, i1 = 0;
#pragma unroll
        for (int e = 0; e < NEXP; e++) {
            float l = acc[e] + br[e];
            if (l > v0) { v1 = v0; i1 = i0; v0 = l; i0 = e; }
            else if (l > v1) { v1 = l; i1 = e; }
        }
        float t = expf(v1 - v0);
        float inv = 1.f / (1.f + t);
        int p0 = atomicAdd(&g_cnt[i0], 1);
        g_etok[i0 * CAP + p0] = tok * 2;
        g_egate[i0 * CAP + p0] = inv;
        int p1 = atomicAdd(&g_cnt[i1], 1);
        g_etok[i1 * CAP + p1] = tok * 2 + 1;
        g_egate[i1 * CAP + p1] = t * inv;
    }
}

// ---------------- fp16 grouped GEMM (ldmatrix + cp.async pipeline) ------------
// MODE 1: g_h(fp16) = relu(gather(g_xh) @ g_w1h[e]^T + b1[e])   KITER=16, kz=0
// MODE 2: ypart[kz] = gate*(g_h @ g_w2h[e]^T [+ b2])            KITER=32, kz=0,1
template <int KITER, int MODE>
__global__ __launch_bounds__(256, 2) void moe_hgemm(
    const __half* __restrict__ Ah, const __half* __restrict__ Bh,
    const float* __restrict__ bias) {
    const int NTOT = (MODE == 1) ? HDIM : DDIM;
    const int KFULL = (MODE == 1) ? DDIM : HDIM;
    int z = blockIdx.z;
    int e = z & 7, kz = (MODE == 2) ? (z >> 3) : 0;
    int cnt = g_cnt[e];
    int m0 = blockIdx.y * TM;
    if (m0 >= cnt) return;
    int n0 = blockIdx.x * TN;
    int off = 0;
#pragma unroll
    for (int q = 0; q < NEXP; q++) off += (q < e) ? g_cnt[q] : 0;
    int k0g = kz * (KITER * BKH);

    extern __shared__ __align__(1024) char sm[];
    __shared__ int sRow[TM];
    __shared__ float sGate[TM];

    int tid = threadIdx.x;
    for (int r = tid; r < TM; r += 256) {
        int slot = m0 + r;
        if (MODE == 1) {
            sRow[r] = (slot < cnt) ? (g_etok[e * CAP + slot] >> 1) : 0;
        } else {
            sRow[r] = (slot < cnt) ? g_etok[e * CAP + slot] : 0;
            sGate[r] = (slot < cnt) ? g_egate[e * CAP + slot] : 0.f;
        }
    }
    __syncthreads();

    // ---- producer mapping ----
    int prow = tid >> 1;
    int c0 = (tid & 1) * 4;
    int psw = prow & 7;
    const __half* aRow;
    if (MODE == 1) {
        aRow = Ah + (size_t)sRow[prow] * KFULL + k0g;
    } else {
        int sg = off + m0 + prow;
        if (sg > NSLOT - 1) sg = NSLOT - 1;
        aRow = g_h + (size_t)sg * KFULL + k0g;
    }
    const __half* bRow = Bh + (size_t)e * NTOT * KFULL +
                         (size_t)(n0 + prow) * KFULL + k0g;
    uint32_t sb = smem_u32(sm);
    uint32_t aDstBase = sb + prow * 128;
    uint32_t bDstBase = sb + ASTAGE_B + prow * 128;

#define ISSUE(c)                                                      \
    {                                                                 \
        uint32_t so_ = ((c) % NPIPE) * STAGE_B;                       \
        const __half* ag_ = aRow + (c)*BKH;                           \
        const __half* bg_ = bRow + (c)*BKH;                           \
        _Pragma("unroll")                                             \
        for (int j = 0; j < 4; j++) {                                 \
            int cc = c0 + j;                                          \
            int sc = cc ^ psw;                                        \
            CPASYNC16(aDstBase + so_ + sc * 16, ag_ + cc * 8);        \
            CPASYNC16(bDstBase + so_ + sc * 16, bg_ + cc * 8);        \
        }                                                             \
    }

#pragma unroll
    for (int c = 0; c < NPIPE - 1; c++) {
        ISSUE(c);
        CP_COMMIT();
    }

    // ---- consumer mapping ----
    int lane = tid & 31, wid = tid >> 5;
    int wm = wid >> 2, wn = wid & 3;
    int s = lane & 7;
    int aChunkBit = lane >> 4;
    uint32_t aByte = (uint32_t)(wm * 64 + (lane & 7) + ((lane >> 3) & 1) * 8) * 128;
    int bChunkBit = (lane >> 3) & 1;
    uint32_t bByte = ASTAGE_B +
                     (uint32_t)(wn * 32 + ((lane >> 4) & 1) * 8 + (lane & 7)) * 128;

    float acc[4][4][4];
#pragma unroll
    for (int mt = 0; mt < 4; mt++)
#pragma unroll
        for (int nt = 0; nt < 4; nt++)
#pragma unroll
            for (int v = 0; v < 4; v++) acc[mt][nt][v] = 0.f;

    for (int c = 0; c < KITER; c++) {
        CP_WAIT(NPIPE - 2);
        __syncthreads();
        if (c + NPIPE - 1 < KITER) ISSUE(c + NPIPE - 1);
        CP_COMMIT();

        uint32_t stb = sb + (c % NPIPE) * STAGE_B;
#pragma unroll
        for (int kt = 0; kt < 4; kt++) {
            unsigned af[4][4], bf[4][2];
#pragma unroll
            for (int mt = 0; mt < 4; mt++) {
                uint32_t ad = stb + aByte + mt * 2048 +
                              (uint32_t)(((2 * kt + aChunkBit) ^ s) << 4);
                LDSM_X4(af[mt][0], af[mt][1], af[mt][2], af[mt][3], ad);
            }
#pragma unroll
            for (int p = 0; p < 2; p++) {
                uint32_t bd = stb + bByte + p * 2048 +
                              (uint32_t)(((2 * kt + bChunkBit) ^ s) << 4);
                LDSM_X4(bf[2 * p][0], bf[2 * p][1], bf[2 * p + 1][0],
                        bf[2 * p + 1][1], bd);
            }
#pragma unroll
            for (int mt = 0; mt < 4; mt++)
#pragma unroll
                for (int nt = 0; nt < 4; nt++)
                    mma16816(acc[mt][nt], af[mt], bf[nt]);
        }
    }
#undef ISSUE

    // ---- epilogue ----
    int g = lane >> 2, tig = lane & 3;
#pragma unroll
    for (int mt = 0; mt < 4; mt++) {
#pragma unroll
        for (int hh = 0; hh < 2; hh++) {
            int r = wm * 64 + mt * 16 + g + 8 * hh;
            int slot = m0 + r;
            if (slot >= cnt) continue;
            if (MODE == 1) {
                __half* orow = g_h + (size_t)(off + slot) * HDIM + n0;
                const float* bp = bias + e * HDIM + n0;
#pragma unroll
                for (int nt = 0; nt < 4; nt++) {
                    int col = wn * 32 + nt * 8 + 2 * tig;
                    float v0 = fmaxf(acc[mt][nt][hh * 2 + 0] + bp[col], 0.f);
                    float v1 = fmaxf(acc[mt][nt][hh * 2 + 1] + bp[col + 1], 0.f);
                    __half2 hv = __floats2half2_rn(v0, v1);
                    *(__half2*)(orow + col) = hv;
                }
            } else {
                int packed = sRow[r];
                float gte = sGate[r];
                float* orow = g_ypart + ((size_t)kz * NSLOT + packed) * DDIM + n0;
                const float* bp = bias + e * DDIM + n0;
#pragma unroll
                for (int nt = 0; nt < 4; nt++) {
                    int col = wn * 32 + nt * 8 + 2 * tig;
                    float v0 = acc[mt][nt][hh * 2 + 0];
                    float v1 = acc[mt][nt][hh * 2 + 1];
                    if (kz == 0) { v0 += bp[col]; v1 += bp[col + 1]; }
                    *(float2*)(orow + col) = make_float2(v0 * gte, v1 * gte);
                }
            }
        }
    }
}

// ---------------- combine: sum 2 k-choices x 2 K-splits -----------------------
__global__ void combine_kernel(float* __restrict__ out) {
    int i = blockIdx.x * blockDim.x + threadIdx.x;
    const int TOT = NTOK * DDIM / 4;
    if (i >= TOT) return;
    int n = i / (DDIM / 4);
    int dg = i % (DDIM / 4);
    const float4* yp = (const float4*)g_ypart;
    const size_t RP = DDIM / 4;
    float4 a0 = yp[(size_t)(2 * n) * RP + dg];
    float4 a1 = yp[(size_t)(2 * n + 1) * RP + dg];
    float4 b0 = yp[((size_t)NSLOT + 2 * n) * RP + dg];
    float4 b1 = yp[((size_t)NSLOT + 2 * n + 1) * RP + dg];
    float4 r;
    r.x = (a0.x + b0.x) + (a1.x + b1.x);
    r.y = (a0.y + b0.y) + (a1.y + b1.y);
    r.z = (a0.z + b0.z) + (a1.z + b1.z);
    r.w = (a0.w + b0.w) + (a1.w + b1.w);
    ((float4*)out)[i] = r;
}

// ---------------- launch -----------------------------------------------------
extern "C" void kernel_launch(void* const* d_in, const int* in_sizes, int n_in,
                              void* d_out, int out_size) {
    const float* x  = (const float*)d_in[0];
    const float* Wr = (const float*)d_in[1];
    const float* br = (const float*)d_in[2];
    const float* W1 = (const float*)d_in[3];
    const float* b1 = (const float*)d_in[4];
    const float* W2 = (const float*)d_in[5];
    const float* b2 = (const float*)d_in[6];
    float* out = (float*)d_out;
    (void)in_sizes; (void)n_in; (void)out_size;

    cudaFuncSetAttribute(moe_hgemm<16, 1>,
                         cudaFuncAttributeMaxDynamicSharedMemorySize, SMEM_BYTES);
    cudaFuncSetAttribute(moe_hgemm<32, 2>,
                         cudaFuncAttributeMaxDynamicSharedMemorySize, SMEM_BYTES);

    __half *w1h, *w2h;
    cudaGetSymbolAddress((void**)&w1h, g_w1h);
    cudaGetSymbolAddress((void**)&w2h, g_w2h);
    {
        int n8 = NEXP * HDIM * DDIM / 8;
        cvt_kernel<1><<<(n8 + 255) / 256, 256>>>(W1, w1h, n8);   // also inits g_cnt
        cvt_kernel<0><<<(n8 + 255) / 256, 256>>>(W2, w2h, n8);
    }
    router_kernel<<<NTOK / 8, 256>>>(x, Wr, br);                 // also converts x

    __half* xh;
    cudaGetSymbolAddress((void**)&xh, g_xh);
    dim3 g1(HDIM / TN, NTOK / TM, NEXP);        // 32 x 32 x 8
    moe_hgemm<16, 1><<<g1, 256, SMEM_BYTES>>>(xh, w1h, b1);

    dim3 g2(DDIM / TN, NTOK / TM, NEXP * 2);    // 8 x 32 x 16 (split-K=2)
    moe_hgemm<32, 2><<<g2, 256, SMEM_BYTES>>>(nullptr, w2h, b2);

    combine_kernel<<<(NTOK * DDIM / 4 + 255) / 256, 256>>>(out);
}